// round 2
// baseline (speedup 1.0000x reference)
#include <cuda_runtime.h>
#include <cuda_bf16.h>
#include <cstdint>

typedef unsigned long long u64;

// ---------------- constants ----------------
#define LSEQ     2048
#define DIMV     32
#define SEGS     4
#define SEG_ROWS 512
#define CHUNK_R  128
#define NCHUNK   4
#define NBUF     3
#define THREADS  256
#define NPAIRS   496
#define OUTW     528
#define CHUNK_BYTES (CHUNK_R * DIMV * 4)   // 16384

// partial C scratch: [B][SEGS][32*32] fp32 = 8 MB
__device__ float g_part[512 * SEGS * 1024];

// ---------------- f32x2 helpers ----------------
__device__ __forceinline__ u64 fma2(u64 a, u64 b, u64 c) {
    u64 d;
    asm("fma.rn.f32x2 %0, %1, %2, %3;" : "=l"(d) : "l"(a), "l"(b), "l"(c));
    return d;
}
__device__ __forceinline__ u64 add2(u64 a, u64 b) {
    u64 d;
    asm("add.rn.f32x2 %0, %1, %2;" : "=l"(d) : "l"(a), "l"(b));
    return d;
}
__device__ __forceinline__ u64 splat(float x) {
    u64 r;
    asm("mov.b64 %0, {%1, %1};" : "=l"(r) : "f"(x));
    return r;
}
__device__ __forceinline__ u64 pk2(float x, float y) {
    u64 r;
    asm("mov.b64 %0, {%1, %2};" : "=l"(r) : "f"(x), "f"(y));
    return r;
}

// ---------------- shared-memory access (32-bit addresses) ----------------
__device__ __forceinline__ void lds_v2u64(u64& b0, u64& b1, unsigned addr) {
    asm volatile("ld.shared.v2.b64 {%0, %1}, [%2];" : "=l"(b0), "=l"(b1) : "r"(addr));
}
__device__ __forceinline__ float4 lds_f4(unsigned addr) {
    float4 v;
    asm volatile("ld.shared.v4.f32 {%0, %1, %2, %3}, [%4];"
                 : "=f"(v.x), "=f"(v.y), "=f"(v.z), "=f"(v.w) : "r"(addr));
    return v;
}

// ---------------- cp.async ----------------
__device__ __forceinline__ void cp_commit() { asm volatile("cp.async.commit_group;"); }
template <int N>
__device__ __forceinline__ void cp_wait() { asm volatile("cp.async.wait_group %0;" ::"n"(N)); }

__device__ __forceinline__ void copy_chunk(const float* __restrict__ gseg,
                                           unsigned sb_addr, int c, int tid) {
    const char* gsrc = (const char*)(gseg + (size_t)c * CHUNK_R * DIMV);
#pragma unroll
    for (int i = 0; i < 4; i++) {
        unsigned off = (unsigned)tid * 16u + (unsigned)i * 4096u;
        asm volatile("cp.async.cg.shared.global [%0], [%1], 16;" ::"r"(sb_addr + off),
                     "l"(gsrc + off));
    }
}

// ---------------- macro step: 8x8 outer product, b from smem ----------------
__device__ __forceinline__ void macro_b(u64* acc, u64 b0, u64 b1, u64 b2, u64 b3,
                                        float4 a0, float4 a1) {
    float av[8] = {a0.x, a0.y, a0.z, a0.w, a1.x, a1.y, a1.z, a1.w};
#pragma unroll
    for (int ii = 0; ii < 8; ii++) {
        u64 s = splat(av[ii]);
        acc[ii * 4 + 0] = fma2(s, b0, acc[ii * 4 + 0]);
        acc[ii * 4 + 1] = fma2(s, b1, acc[ii * 4 + 1]);
        acc[ii * 4 + 2] = fma2(s, b2, acc[ii * 4 + 2]);
        acc[ii * 4 + 3] = fma2(s, b3, acc[ii * 4 + 3]);
    }
}
__device__ __forceinline__ void macro_ab(u64* acc, unsigned aaddr, unsigned baddr) {
    float4 a0 = lds_f4(aaddr);
    float4 a1 = lds_f4(aaddr + 16);
    u64 b0, b1, b2, b3;
    lds_v2u64(b0, b1, baddr);
    lds_v2u64(b2, b3, baddr + 16);
    macro_b(acc, b0, b1, b2, b3, a0, a1);
}

// ---------------- kernel 1: partial C per (batch, segment) ----------------
__global__ __launch_bounds__(THREADS, 2) void logsig_part_kernel(const float* __restrict__ x) {
    const int b    = blockIdx.x >> 2;
    const int s    = blockIdx.x & 3;
    const int tid  = threadIdx.x;
    const int w    = tid >> 5;
    const int lane = tid & 31;
    const int h    = lane >> 4;       // which l within the macro pair
    const int r    = lane & 15;       // tile id within 32x32
    const int i0   = (r & 3) * 8;
    const int j0   = (r >> 2) * 8;

    __shared__ float sbuf[NBUF][CHUNK_R][DIMV];  // 48 KB

    const float* gseg = x + ((size_t)b * LSEQ + (size_t)s * SEG_ROWS) * DIMV;
    unsigned sbase = (unsigned)__cvta_generic_to_shared(&sbuf[0][0][0]);

    // prologue: prefetch chunks 0..2
    copy_chunk(gseg, sbase + 0 * CHUNK_BYTES, 0, tid); cp_commit();
    copy_chunk(gseg, sbase + 1 * CHUNK_BYTES, 1, tid); cp_commit();
    copy_chunk(gseg, sbase + 2 * CHUNK_BYTES, 2, tid); cp_commit();

    // cross-segment boundary row in registers (warp 7, half 1 only, s<3)
    u64 pb0 = 0, pb1 = 0, pb2 = 0, pb3 = 0;
    if (w == 7 && h == 1 && s < SEGS - 1) {
        const float* gb = gseg + (size_t)SEG_ROWS * DIMV + j0;
        float4 t0 = *(const float4*)gb;
        float4 t1 = *(const float4*)(gb + 4);
        pb0 = pk2(t0.x, t0.y); pb1 = pk2(t0.z, t0.w);
        pb2 = pk2(t1.x, t1.y); pb3 = pk2(t1.z, t1.w);
    }

    u64 acc[32];
#pragma unroll
    for (int i = 0; i < 32; i++) acc[i] = 0ull;

#pragma unroll 1
    for (int c = 0; c < NCHUNK; c++) {
        if (c < 2) cp_wait<1>(); else cp_wait<0>();
        __syncthreads();

        unsigned buf   = sbase + (unsigned)(c % NBUF) * CHUNK_BYTES;
        unsigned aaddr = buf + (unsigned)(w * 16 + h) * 128u + (unsigned)i0 * 4u;
        unsigned baddr = buf + (unsigned)(w * 16 + h + 1) * 128u + (unsigned)j0 * 4u;

#pragma unroll
        for (int m = 0; m < 7; m++) {
            macro_ab(acc, aaddr, baddr);
            aaddr += 256u; baddr += 256u;
        }
        // m == 7: b-row may cross the chunk boundary for (w==7, h==1)
        bool tail = (w == 7) && (h == 1);
        if (!tail) {
            macro_ab(acc, aaddr, baddr);
        } else if (c < NCHUNK - 1) {
            unsigned nb = sbase + (unsigned)((c + 1) % NBUF) * CHUNK_BYTES + (unsigned)j0 * 4u;
            macro_ab(acc, aaddr, nb);
        } else if (s < SEGS - 1) {
            float4 a0 = lds_f4(aaddr);
            float4 a1 = lds_f4(aaddr + 16);
            macro_b(acc, pb0, pb1, pb2, pb3, a0, a1);
        }
        // (s==SEGS-1, c==NCHUNK-1, w==7, h==1: step l=2047 doesn't exist)

        __syncthreads();
        if (c == 0) { copy_chunk(gseg, sbase, 3, tid); cp_commit(); }
    }

    // combine the two halves: lane r += lane r+16 (same tile, other l-parity)
#pragma unroll
    for (int k = 0; k < 32; k++) {
        u64 o = __shfl_down_sync(0xffffffffu, acc[k], 16);
        if (h == 0) acc[k] = add2(acc[k], o);
    }

    // per-warp partials -> smem (reuse chunk buffers; all compute synced above)
    float* pr = &sbuf[0][0][0];
    if (h == 0) {
#pragma unroll
        for (int ii = 0; ii < 8; ii++) {
#pragma unroll
            for (int jp = 0; jp < 4; jp++) {
                *(u64*)&pr[w * 1024 + (i0 + ii) * 32 + j0 + 2 * jp] = acc[ii * 4 + jp];
            }
        }
    }
    __syncthreads();

    const int e0 = tid * 4;
    float4 sum = make_float4(0.f, 0.f, 0.f, 0.f);
#pragma unroll
    for (int ww = 0; ww < 8; ww++) {
        float4 v = *(const float4*)&pr[ww * 1024 + e0];
        sum.x += v.x; sum.y += v.y; sum.z += v.z; sum.w += v.w;
    }
    *(float4*)&g_part[((size_t)b * SEGS + s) * 1024 + e0] = sum;
}

// ---------------- kernel 2: combine + outputs ----------------
__global__ __launch_bounds__(THREADS) void logsig_final_kernel(const float* __restrict__ x,
                                                               float* __restrict__ out) {
    const int b   = blockIdx.x;
    const int tid = threadIdx.x;

    __shared__ float Cs[1024];
    __shared__ float x0s[DIMV];
    __shared__ float l1s[DIMV];

    const int e0 = tid * 4;
    float4 sum = make_float4(0.f, 0.f, 0.f, 0.f);
#pragma unroll
    for (int s = 0; s < SEGS; s++) {
        float4 v = *(const float4*)&g_part[((size_t)b * SEGS + s) * 1024 + e0];
        sum.x += v.x; sum.y += v.y; sum.z += v.z; sum.w += v.w;
    }
    *(float4*)&Cs[e0] = sum;

    if (tid < DIMV) {
        float x0 = x[(size_t)b * LSEQ * DIMV + tid];
        float xl = x[(size_t)b * LSEQ * DIMV + (size_t)(LSEQ - 1) * DIMV + tid];
        float l1 = xl - x0;
        x0s[tid] = x0;
        l1s[tid] = l1;
        out[(size_t)b * OUTW + tid] = l1;
    }
    __syncthreads();

#pragma unroll
    for (int p = tid; p < NPAIRS; p += THREADS) {
        // closed-form inversion of p -> (i, j), i<j, row-major upper triangle
        float f = (63.0f - sqrtf((float)(3969 - 8 * p))) * 0.5f;
        int i = (int)f;
        int base = i * (63 - i) / 2;
        if (base > p) { i--; base = i * (63 - i) / 2; }
        else {
            int nb = (i + 1) * (62 - i) / 2;
            if (nb <= p) { i++; base = nb; }
        }
        int j = i + 1 + (p - base);
        float val = 0.5f * ((Cs[i * 32 + j] - Cs[j * 32 + i])
                            - x0s[i] * l1s[j] + x0s[j] * l1s[i]);
        out[(size_t)b * OUTW + DIMV + p] = val;
    }
}

// ---------------- launch ----------------
extern "C" void kernel_launch(void* const* d_in, const int* in_sizes, int n_in,
                              void* d_out, int out_size) {
    const float* x = (const float*)d_in[0];
    float* out = (float*)d_out;
    const int B = in_sizes[0] / (LSEQ * DIMV);  // 512

    logsig_part_kernel<<<B * SEGS, THREADS>>>(x);
    logsig_final_kernel<<<B, THREADS>>>(x, out);
}

// round 3
// speedup vs baseline: 1.1127x; 1.1127x over previous
#include <cuda_runtime.h>
#include <cuda_bf16.h>
#include <cstdint>

typedef unsigned long long u64;

// ---------------- constants ----------------
#define LSEQ     2048
#define DIMV     32
#define SEGS     4
#define SEG_ROWS 512
#define CHUNK_R  128
#define NCHUNK   4
#define NBUF     3
#define THREADS  256
#define NPAIRS   496
#define OUTW     528
#define CHUNK_BYTES (CHUNK_R * DIMV * 4)   // 16384

// partial C scratch: [B][SEGS][32*32] fp32 = 8 MB
__device__ float g_part[512 * SEGS * 1024];

// ---------------- f32x2 helpers ----------------
__device__ __forceinline__ u64 fma2(u64 a, u64 b, u64 c) {
    u64 d;
    asm("fma.rn.f32x2 %0, %1, %2, %3;" : "=l"(d) : "l"(a), "l"(b), "l"(c));
    return d;
}
__device__ __forceinline__ u64 add2(u64 a, u64 b) {
    u64 d;
    asm("add.rn.f32x2 %0, %1, %2;" : "=l"(d) : "l"(a), "l"(b));
    return d;
}
__device__ __forceinline__ u64 splat(float x) {
    u64 r;
    asm("mov.b64 %0, {%1, %1};" : "=l"(r) : "f"(x));
    return r;
}
__device__ __forceinline__ u64 pk2(float x, float y) {
    u64 r;
    asm("mov.b64 %0, {%1, %2};" : "=l"(r) : "f"(x), "f"(y));
    return r;
}

// ---------------- shared-memory access (32-bit addresses) ----------------
__device__ __forceinline__ void lds_v2u64(u64& b0, u64& b1, unsigned addr) {
    asm volatile("ld.shared.v2.b64 {%0, %1}, [%2];" : "=l"(b0), "=l"(b1) : "r"(addr));
}
__device__ __forceinline__ float4 lds_f4(unsigned addr) {
    float4 v;
    asm volatile("ld.shared.v4.f32 {%0, %1, %2, %3}, [%4];"
                 : "=f"(v.x), "=f"(v.y), "=f"(v.z), "=f"(v.w) : "r"(addr));
    return v;
}

// ---------------- cp.async ----------------
__device__ __forceinline__ void cp_commit() { asm volatile("cp.async.commit_group;"); }
template <int N>
__device__ __forceinline__ void cp_wait() { asm volatile("cp.async.wait_group %0;" ::"n"(N)); }

__device__ __forceinline__ void copy_chunk(const float* __restrict__ gseg,
                                           unsigned sb_addr, int c, int tid) {
    const char* gsrc = (const char*)(gseg + (size_t)c * CHUNK_R * DIMV);
#pragma unroll
    for (int i = 0; i < 4; i++) {
        unsigned off = (unsigned)tid * 16u + (unsigned)i * 4096u;
        asm volatile("cp.async.cg.shared.global [%0], [%1], 16;" ::"r"(sb_addr + off),
                     "l"(gsrc + off));
    }
}

// ---------------- macro step: 8x8 outer product, b from smem ----------------
__device__ __forceinline__ void macro_b(u64* acc, u64 b0, u64 b1, u64 b2, u64 b3,
                                        float4 a0, float4 a1) {
    float av[8] = {a0.x, a0.y, a0.z, a0.w, a1.x, a1.y, a1.z, a1.w};
#pragma unroll
    for (int ii = 0; ii < 8; ii++) {
        u64 s = splat(av[ii]);
        acc[ii * 4 + 0] = fma2(s, b0, acc[ii * 4 + 0]);
        acc[ii * 4 + 1] = fma2(s, b1, acc[ii * 4 + 1]);
        acc[ii * 4 + 2] = fma2(s, b2, acc[ii * 4 + 2]);
        acc[ii * 4 + 3] = fma2(s, b3, acc[ii * 4 + 3]);
    }
}
__device__ __forceinline__ void macro_ab(u64* acc, unsigned aaddr, unsigned baddr) {
    float4 a0 = lds_f4(aaddr);
    float4 a1 = lds_f4(aaddr + 16);
    u64 b0, b1, b2, b3;
    lds_v2u64(b0, b1, baddr);
    lds_v2u64(b2, b3, baddr + 16);
    macro_b(acc, b0, b1, b2, b3, a0, a1);
}

// ---------------- kernel 1: partial C per (batch, segment) ----------------
__global__ __launch_bounds__(THREADS, 2) void logsig_part_kernel(const float* __restrict__ x) {
    const int b    = blockIdx.x >> 2;
    const int s    = blockIdx.x & 3;
    const int tid  = threadIdx.x;
    const int w    = tid >> 5;
    const int lane = tid & 31;
    const int h    = lane >> 4;       // which l within the macro pair
    const int r    = lane & 15;       // tile id within 32x32
    const int i0   = (r & 3) * 8;
    const int j0   = (r >> 2) * 8;

    __shared__ float sbuf[NBUF][CHUNK_R][DIMV];  // 48 KB

    const float* gseg = x + ((size_t)b * LSEQ + (size_t)s * SEG_ROWS) * DIMV;
    unsigned sbase = (unsigned)__cvta_generic_to_shared(&sbuf[0][0][0]);

    // prologue: prefetch chunks 0..2
    copy_chunk(gseg, sbase + 0 * CHUNK_BYTES, 0, tid); cp_commit();
    copy_chunk(gseg, sbase + 1 * CHUNK_BYTES, 1, tid); cp_commit();
    copy_chunk(gseg, sbase + 2 * CHUNK_BYTES, 2, tid); cp_commit();

    // cross-segment boundary row in registers (warp 7, half 1 only, s<3)
    u64 pb0 = 0, pb1 = 0, pb2 = 0, pb3 = 0;
    if (w == 7 && h == 1 && s < SEGS - 1) {
        const float* gb = gseg + (size_t)SEG_ROWS * DIMV + j0;
        float4 t0 = *(const float4*)gb;
        float4 t1 = *(const float4*)(gb + 4);
        pb0 = pk2(t0.x, t0.y); pb1 = pk2(t0.z, t0.w);
        pb2 = pk2(t1.x, t1.y); pb3 = pk2(t1.z, t1.w);
    }

    u64 acc[32];
#pragma unroll
    for (int i = 0; i < 32; i++) acc[i] = 0ull;

#pragma unroll 1
    for (int c = 0; c < NCHUNK; c++) {
        if (c < 2) cp_wait<1>(); else cp_wait<0>();
        __syncthreads();

        unsigned buf   = sbase + (unsigned)(c % NBUF) * CHUNK_BYTES;
        unsigned aaddr = buf + (unsigned)(w * 16 + h) * 128u + (unsigned)i0 * 4u;
        unsigned baddr = buf + (unsigned)(w * 16 + h + 1) * 128u + (unsigned)j0 * 4u;

#pragma unroll
        for (int m = 0; m < 7; m++) {
            macro_ab(acc, aaddr, baddr);
            aaddr += 256u; baddr += 256u;
        }
        // m == 7: b-row may cross the chunk boundary for (w==7, h==1)
        bool tail = (w == 7) && (h == 1);
        if (!tail) {
            macro_ab(acc, aaddr, baddr);
        } else if (c < NCHUNK - 1) {
            unsigned nb = sbase + (unsigned)((c + 1) % NBUF) * CHUNK_BYTES + (unsigned)j0 * 4u;
            macro_ab(acc, aaddr, nb);
        } else if (s < SEGS - 1) {
            float4 a0 = lds_f4(aaddr);
            float4 a1 = lds_f4(aaddr + 16);
            macro_b(acc, pb0, pb1, pb2, pb3, a0, a1);
        }
        // (s==SEGS-1, c==NCHUNK-1, w==7, h==1: step l=2047 doesn't exist)

        __syncthreads();
        if (c == 0) { copy_chunk(gseg, sbase, 3, tid); cp_commit(); }
    }

    // combine the two halves: lane r += lane r+16 (same tile, other l-parity)
#pragma unroll
    for (int k = 0; k < 32; k++) {
        u64 o = __shfl_down_sync(0xffffffffu, acc[k], 16);
        if (h == 0) acc[k] = add2(acc[k], o);
    }

    // per-warp partials -> smem (reuse chunk buffers; all compute synced above)
    float* pr = &sbuf[0][0][0];
    if (h == 0) {
#pragma unroll
        for (int ii = 0; ii < 8; ii++) {
#pragma unroll
            for (int jp = 0; jp < 4; jp++) {
                *(u64*)&pr[w * 1024 + (i0 + ii) * 32 + j0 + 2 * jp] = acc[ii * 4 + jp];
            }
        }
    }
    __syncthreads();

    const int e0 = tid * 4;
    float4 sum = make_float4(0.f, 0.f, 0.f, 0.f);
#pragma unroll
    for (int ww = 0; ww < 8; ww++) {
        float4 v = *(const float4*)&pr[ww * 1024 + e0];
        sum.x += v.x; sum.y += v.y; sum.z += v.z; sum.w += v.w;
    }
    *(float4*)&g_part[((size_t)b * SEGS + s) * 1024 + e0] = sum;
}

// ---------------- kernel 2: combine + outputs ----------------
__global__ __launch_bounds__(THREADS) void logsig_final_kernel(const float* __restrict__ x,
                                                               float* __restrict__ out) {
    const int b   = blockIdx.x;
    const int tid = threadIdx.x;

    __shared__ float Cs[1024];
    __shared__ float x0s[DIMV];
    __shared__ float l1s[DIMV];

    const int e0 = tid * 4;
    float4 sum = make_float4(0.f, 0.f, 0.f, 0.f);
#pragma unroll
    for (int s = 0; s < SEGS; s++) {
        float4 v = *(const float4*)&g_part[((size_t)b * SEGS + s) * 1024 + e0];
        sum.x += v.x; sum.y += v.y; sum.z += v.z; sum.w += v.w;
    }
    *(float4*)&Cs[e0] = sum;

    if (tid < DIMV) {
        float x0 = x[(size_t)b * LSEQ * DIMV + tid];
        float xl = x[(size_t)b * LSEQ * DIMV + (size_t)(LSEQ - 1) * DIMV + tid];
        float l1 = xl - x0;
        x0s[tid] = x0;
        l1s[tid] = l1;
        out[(size_t)b * OUTW + tid] = l1;
    }
    __syncthreads();

#pragma unroll
    for (int p = tid; p < NPAIRS; p += THREADS) {
        // closed-form inversion of p -> (i, j), i<j, row-major upper triangle
        float f = (63.0f - sqrtf((float)(3969 - 8 * p))) * 0.5f;
        int i = (int)f;
        int base = i * (63 - i) / 2;
        if (base > p) { i--; base = i * (63 - i) / 2; }
        else {
            int nb = (i + 1) * (62 - i) / 2;
            if (nb <= p) { i++; base = nb; }
        }
        int j = i + 1 + (p - base);
        float val = 0.5f * ((Cs[i * 32 + j] - Cs[j * 32 + i])
                            - x0s[i] * l1s[j] + x0s[j] * l1s[i]);
        out[(size_t)b * OUTW + DIMV + p] = val;
    }
}

// ---------------- launch ----------------
extern "C" void kernel_launch(void* const* d_in, const int* in_sizes, int n_in,
                              void* d_out, int out_size) {
    const float* x = (const float*)d_in[0];
    float* out = (float*)d_out;
    const int B = in_sizes[0] / (LSEQ * DIMV);  // 512

    logsig_part_kernel<<<B * SEGS, THREADS>>>(x);
    logsig_final_kernel<<<B, THREADS>>>(x, out);
}